// round 12
// baseline (speedup 1.0000x reference)
#include <cuda_runtime.h>
#include <cuda_fp16.h>
#include <cstdint>
#include <cstddef>

#define N_NODES 100000
#define B_BATCH 20000
#define K_NBR   10
#define F_DIM   256
#define H_DIM   128

// ---------------------------------------------------------------------------
// Device scratch
// ---------------------------------------------------------------------------
__device__ __half g_tab[(size_t)N_NODES * 384];  // [q|k|v] fp16, 76.8 MB
__device__ uint2 g_Ba[3 * 16 * 512];             // fp16 B fragments, GEMM1
__device__ uint2 g_Bb[3 *  8 * 512];             // fp16 B fragments, GEMM2

// ---------------------------------------------------------------------------
// Helpers
// ---------------------------------------------------------------------------
__device__ __forceinline__ uint32_t smem_u32(const void* p) {
    uint32_t a;
    asm("{ .reg .u64 t; cvta.to.shared.u64 t, %1; cvt.u32.u64 %0, t; }"
        : "=r"(a) : "l"(p));
    return a;
}
__device__ __forceinline__ uint32_t pack_f16x2(float a, float b) {
    half2 h = __floats2half2_rn(a, b);
    return *(uint32_t*)&h;
}
__device__ __forceinline__ float tanh_fast(float x) {
    float y;
    asm("tanh.approx.f32 %0, %1;" : "=f"(y) : "f"(x));
    return y;
}
__device__ __forceinline__ void ldm4(uint32_t* r, uint32_t addr) {
    asm volatile("ldmatrix.sync.aligned.m8n8.x4.shared.b16 {%0,%1,%2,%3}, [%4];"
                 : "=r"(r[0]), "=r"(r[1]), "=r"(r[2]), "=r"(r[3]) : "r"(addr));
}
__device__ __forceinline__ void mma16816(float* d, const uint32_t* a,
                                         uint32_t b0, uint32_t b1) {
    asm volatile(
        "mma.sync.aligned.m16n8k16.row.col.f32.f16.f16.f32 "
        "{%0,%1,%2,%3}, {%4,%5,%6,%7}, {%8,%9}, {%0,%1,%2,%3};"
        : "+f"(d[0]), "+f"(d[1]), "+f"(d[2]), "+f"(d[3])
        : "r"(a[0]), "r"(a[1]), "r"(a[2]), "r"(a[3]), "r"(b0), "r"(b1));
}

// ---------------------------------------------------------------------------
// Kernel 0: prepack weights into mma B-fragment layout (fp16, single term).
// ---------------------------------------------------------------------------
__global__ void __launch_bounds__(256) prep_weights_kernel(
    const float* __restrict__ W1a, const float* __restrict__ W1b,
    const float* __restrict__ W2a, const float* __restrict__ W2b,
    const float* __restrict__ W3a, const float* __restrict__ W3b)
{
    __shared__ float st[16][68];
    const float* Wa[3] = {W1a, W2a, W3a};
    const float* Wb[3] = {W1b, W2b, W3b};

    const int bx2  = blockIdx.x >> 1;
    const int half = blockIdx.x & 1;
    const int tid  = threadIdx.x;
    const float* W;
    uint2* dstbase;
    int ks;
    if (bx2 < 48) {
        int p = bx2 >> 4; ks = bx2 & 15;
        W = Wa[p];
        dstbase = g_Ba + (size_t)(p * 16 + ks) * 512;
    } else {
        int i = bx2 - 48;
        int p = i >> 3; ks = i & 7;
        W = Wb[p];
        dstbase = g_Bb + (size_t)(p * 8 + ks) * 512;
    }

    const float* src = W + (size_t)ks * 16 * H_DIM + half * 64;
    {
        int r  = tid >> 4;
        int c4 = tid & 15;
        float4 v = *(const float4*)(src + r * H_DIM + c4 * 4);
        st[r][c4 * 4 + 0] = v.x;
        st[r][c4 * 4 + 1] = v.y;
        st[r][c4 * 4 + 2] = v.z;
        st[r][c4 * 4 + 3] = v.w;
    }
    __syncthreads();

    {
        int e    = half * 256 + tid;
        int nt   = e >> 5;
        int lane = e & 31;
        int kl   = (lane & 3) * 2;
        int n    = nt * 8 + (lane >> 2) - half * 64;
        uint2 fr;
        fr.x = pack_f16x2(st[kl][n],     st[kl + 1][n]);
        fr.y = pack_f16x2(st[kl + 8][n], st[kl + 9][n]);
        dstbase[e] = fr;
    }
}

// ---------------------------------------------------------------------------
// Kernel 1: HMMA precompute, 3-projection-fused GEMM1.
// CTA = 32 rows x 128 cols, 8 warps: warp wn owns cols wn*16..+15, mt=2.
// GEMM1: one k-loop, A fragments shared across all 3 projections
// (12 MMAs / k-step, 12 independent acc chains). Then 3x GEMM2 passes.
// smem 43 KB -> 2 CTAs/SM. Grid 3125 (exact).
// ---------------------------------------------------------------------------
#define XSTR 264
#define HSTR 136
#define X_OFF 0u
#define H_OFF 16896u                     // 32*264*2
#define H_SZ  8704u                      // 32*136*2 per projection
#define PC_SMEM 43008u                   // X + 3*H

__global__ void __launch_bounds__(256, 2) precompute_mma_kernel(
    const float* __restrict__ embed)
{
    extern __shared__ unsigned char smem[];
    const uint32_t sbase = smem_u32(smem);
    const int tid  = threadIdx.x;
    const int wn   = tid >> 5;           // warp = column strip wn*16..+15
    const int lane = tid & 31;
    const long brow = (long)blockIdx.x * 32;

    const uint32_t loffX = (uint32_t)((lane & 15) * XSTR + (lane >> 4) * 8) * 2;
    const uint32_t loffH = (uint32_t)((lane & 15) * HSTR + (lane >> 4) * 8) * 2;

    // ---- Load X tile [32][256] fp32 -> fp16 smem ----
    for (int i = tid; i < 32 * 64; i += 256) {
        int r  = i >> 6;
        int c4 = i & 63;
        long grow = brow + r;
        float4 v = make_float4(0.f, 0.f, 0.f, 0.f);
        if (grow < N_NODES) v = *(const float4*)(embed + grow * F_DIM + c4 * 4);
        uint32_t off = ((uint32_t)r * XSTR + c4 * 4) * 2;
        *(uint32_t*)(smem + X_OFF + off)     = pack_f16x2(v.x, v.y);
        *(uint32_t*)(smem + X_OFF + off + 4) = pack_f16x2(v.z, v.w);
    }
    __syncthreads();

    const int rbase = (lane >> 2);
    const int cbase = (lane & 3) * 2;

    // ================= Fused GEMM1: X[32,256] @ {W1a,W2a,W3a} =================
    float acc[3][2][2][4];               // [proj][mt][nt][frag]
    #pragma unroll
    for (int p = 0; p < 3; p++)
        #pragma unroll
        for (int mt = 0; mt < 2; mt++)
            #pragma unroll
            for (int nt = 0; nt < 2; nt++)
                #pragma unroll
                for (int c = 0; c < 4; c++) acc[p][mt][nt][c] = 0.f;

    for (int ks = 0; ks < 16; ks++) {
        uint32_t a[2][4];
        uint32_t kb = (uint32_t)ks * 32;
        #pragma unroll
        for (int mt = 0; mt < 2; mt++)
            ldm4(a[mt], sbase + X_OFF + (uint32_t)(mt * 16) * XSTR * 2 + kb + loffX);
        uint2 bf[3][2];
        #pragma unroll
        for (int p = 0; p < 3; p++) {
            const uint2* pb = g_Ba + (size_t)(p * 16 + ks) * 512
                              + (wn * 2) * 32 + lane;
            bf[p][0] = pb[0];
            bf[p][1] = pb[32];
        }
        #pragma unroll
        for (int p = 0; p < 3; p++)
            #pragma unroll
            for (int nt = 0; nt < 2; nt++)
                #pragma unroll
                for (int mt = 0; mt < 2; mt++)
                    mma16816(acc[p][mt][nt], a[mt], bf[p][nt].x, bf[p][nt].y);
    }

    // ---- Epilogue 1: tanh.approx -> 3 H smem buffers (fp16) ----
    #pragma unroll
    for (int p = 0; p < 3; p++) {
        #pragma unroll
        for (int mt = 0; mt < 2; mt++) {
            #pragma unroll
            for (int nt = 0; nt < 2; nt++) {
                int col = wn * 16 + nt * 8 + cbase;
                int r0  = mt * 16 + rbase;
                float t0 = tanh_fast(acc[p][mt][nt][0]);
                float t1 = tanh_fast(acc[p][mt][nt][1]);
                float t2 = tanh_fast(acc[p][mt][nt][2]);
                float t3 = tanh_fast(acc[p][mt][nt][3]);
                uint32_t hb = H_OFF + p * H_SZ;
                uint32_t o0 = hb + ((uint32_t)r0 * HSTR + col) * 2;
                uint32_t o1 = hb + ((uint32_t)(r0 + 8) * HSTR + col) * 2;
                *(uint32_t*)(smem + o0) = pack_f16x2(t0, t1);
                *(uint32_t*)(smem + o1) = pack_f16x2(t2, t3);
            }
        }
    }
    __syncthreads();

    // ================= GEMM2 x3: H_p[32,128] @ Wb_p -> g_tab =================
    for (int p = 0; p < 3; p++) {
        float ac2[2][2][4];
        #pragma unroll
        for (int mt = 0; mt < 2; mt++)
            #pragma unroll
            for (int nt = 0; nt < 2; nt++)
                #pragma unroll
                for (int c = 0; c < 4; c++) ac2[mt][nt][c] = 0.f;

        const uint32_t hb = H_OFF + p * H_SZ;
        for (int ks = 0; ks < 8; ks++) {
            uint32_t a[2][4];
            uint32_t kb = (uint32_t)ks * 32;
            #pragma unroll
            for (int mt = 0; mt < 2; mt++)
                ldm4(a[mt], sbase + hb + (uint32_t)(mt * 16) * HSTR * 2 + kb + loffH);
            const uint2* pb = g_Bb + (size_t)(p * 8 + ks) * 512
                              + (wn * 2) * 32 + lane;
            uint2 b0 = pb[0];
            uint2 b1 = pb[32];
            #pragma unroll
            for (int mt = 0; mt < 2; mt++) {
                mma16816(ac2[mt][0], a[mt], b0.x, b0.y);
                mma16816(ac2[mt][1], a[mt], b1.x, b1.y);
            }
        }

        // ---- Epilogue 2: write q/k/v fp16 into unified table ----
        #pragma unroll
        for (int mt = 0; mt < 2; mt++) {
            #pragma unroll
            for (int nt = 0; nt < 2; nt++) {
                int col = wn * 16 + nt * 8 + cbase;
                long r0 = brow + mt * 16 + rbase;
                if (r0 < N_NODES)
                    *(uint32_t*)(g_tab + r0 * 384 + p * 128 + col) =
                        pack_f16x2(ac2[mt][nt][0], ac2[mt][nt][1]);
                if (r0 + 8 < N_NODES)
                    *(uint32_t*)(g_tab + (r0 + 8) * 384 + p * 128 + col) =
                        pack_f16x2(ac2[mt][nt][2], ac2[mt][nt][3]);
            }
        }
    }
}

// ---------------------------------------------------------------------------
// Kernel 2: warp-autonomous attention (unchanged from round 11).
// ---------------------------------------------------------------------------
__global__ void __launch_bounds__(256) attention_kernel(
    const int* __restrict__ neighbors, float* __restrict__ out)
{
    const int b    = blockIdx.x * 8 + (threadIdx.x >> 5);
    const int lane = threadIdx.x & 31;

    int mynode = 0;
    if (lane < K_NBR) mynode = neighbors[(size_t)b * K_NBR + lane];

    int node[K_NBR];
    #pragma unroll
    for (int j = 0; j < K_NBR; j++)
        node[j] = __shfl_sync(0xffffffffu, mynode, j);

    const int d = lane * 4;

    float4 qv[K_NBR], kv[K_NBR];
    #pragma unroll
    for (int j = 0; j < K_NBR; j++) {
        const __half* base = g_tab + (size_t)node[j] * 384;
        uint2 qr = *(const uint2*)(base + d);
        uint2 kr = *(const uint2*)(base + 128 + d);
        float2 q0 = __half22float2(*(half2*)&qr.x);
        float2 q1 = __half22float2(*(half2*)&qr.y);
        float2 k0 = __half22float2(*(half2*)&kr.x);
        float2 k1 = __half22float2(*(half2*)&kr.y);
        qv[j] = make_float4(q0.x, q0.y, q1.x, q1.y);
        kv[j] = make_float4(k0.x, k0.y, k1.x, k1.y);
    }

    float scol[K_NBR];
    #pragma unroll
    for (int i = 0; i < K_NBR; i++) {
        #pragma unroll
        for (int j = 0; j < K_NBR; j++) {
            float s = qv[i].x * kv[j].x;
            s = fmaf(qv[i].y, kv[j].y, s);
            s = fmaf(qv[i].z, kv[j].z, s);
            s = fmaf(qv[i].w, kv[j].w, s);
            s += __shfl_xor_sync(0xffffffffu, s, 16);
            s += __shfl_xor_sync(0xffffffffu, s, 8);
            s += __shfl_xor_sync(0xffffffffu, s, 4);
            s += __shfl_xor_sync(0xffffffffu, s, 2);
            s += __shfl_xor_sync(0xffffffffu, s, 1);
            if (lane == j) scol[i] = s;
        }
    }

    float4 vv[K_NBR];
    #pragma unroll
    for (int j = 0; j < K_NBR; j++) {
        uint2 vr = *(const uint2*)(g_tab + (size_t)node[j] * 384 + 256 + d);
        float2 v0 = __half22float2(*(half2*)&vr.x);
        float2 v1 = __half22float2(*(half2*)&vr.y);
        vv[j] = make_float4(v0.x, v0.y, v1.x, v1.y);
    }

    float colw = 0.f;
    #pragma unroll
    for (int i = 0; i < K_NBR; i++) {
        float s = (lane < K_NBR) ? scol[i] : -1e30f;
        float m = s;
        m = fmaxf(m, __shfl_xor_sync(0xffffffffu, m, 16));
        m = fmaxf(m, __shfl_xor_sync(0xffffffffu, m, 8));
        m = fmaxf(m, __shfl_xor_sync(0xffffffffu, m, 4));
        m = fmaxf(m, __shfl_xor_sync(0xffffffffu, m, 2));
        m = fmaxf(m, __shfl_xor_sync(0xffffffffu, m, 1));
        float e = (lane < K_NBR) ? __expf(s - m) : 0.f;
        float sum = e;
        sum += __shfl_xor_sync(0xffffffffu, sum, 16);
        sum += __shfl_xor_sync(0xffffffffu, sum, 8);
        sum += __shfl_xor_sync(0xffffffffu, sum, 4);
        sum += __shfl_xor_sync(0xffffffffu, sum, 2);
        sum += __shfl_xor_sync(0xffffffffu, sum, 1);
        colw += e / sum;
    }

    float4 o = make_float4(0.f, 0.f, 0.f, 0.f);
    #pragma unroll
    for (int j = 0; j < K_NBR; j++) {
        float cw = __shfl_sync(0xffffffffu, colw, j);
        o.x = fmaf(cw, vv[j].x, o.x);
        o.y = fmaf(cw, vv[j].y, o.y);
        o.z = fmaf(cw, vv[j].z, o.z);
        o.w = fmaf(cw, vv[j].w, o.w);
    }
    *(float4*)(out + (size_t)b * H_DIM + d) = o;
}

// ---------------------------------------------------------------------------
extern "C" void kernel_launch(void* const* d_in, const int* in_sizes, int n_in,
                              void* d_out, int out_size) {
    const int*   neighbors = (const int*)d_in[0];
    const float* embed     = (const float*)d_in[1];
    const float* W1a       = (const float*)d_in[2];
    const float* W1b       = (const float*)d_in[3];
    const float* W2a       = (const float*)d_in[4];
    const float* W2b       = (const float*)d_in[5];
    const float* W3a       = (const float*)d_in[6];
    const float* W3b       = (const float*)d_in[7];
    float* out = (float*)d_out;

    prep_weights_kernel<<<144, 256>>>(W1a, W1b, W2a, W2b, W3a, W3b);

    cudaFuncSetAttribute(precompute_mma_kernel,
                         cudaFuncAttributeMaxDynamicSharedMemorySize,
                         (int)PC_SMEM);
    const int grid1 = (N_NODES + 31) / 32;     // 3125
    precompute_mma_kernel<<<grid1, 256, PC_SMEM>>>(embed);

    attention_kernel<<<B_BATCH / 8, 256>>>(neighbors, out);
}